// round 15
// baseline (speedup 1.0000x reference)
#include <cuda_runtime.h>
#include <cstdint>

#define NL 10
#define ROWS 128
#define AFFINE_EPS 1e-4f
#define LOG2PI 1.8378770664093453f

__device__ __forceinline__ float frcp(float x) {
    float r;
    asm("rcp.approx.f32 %0, %1;" : "=f"(r) : "f"(x));
    return r;
}

// One coupling layer: z = (z @ W + b) * scale + shift, prod *= s0*s1*s2
__device__ __forceinline__ void layer_step(
    const float* __restrict__ sWB, int i,
    float sr0, float sr1, float sr2,
    float sh0, float sh1, float sh2,
    float& z0, float& z1, float& z2, float& prod)
{
    const float4* L = (const float4*)(sWB + 12 * i);
    float4 p0 = L[0], p1 = L[1], p2 = L[2];
    // W row-major: p0 = W[0..3], p1 = W[4..7], p2.x = W[8], p2.yzw = b
    float y0 = fmaf(z0, p0.x, fmaf(z1, p0.w, fmaf(z2, p1.z, p2.y)));
    float y1 = fmaf(z0, p0.y, fmaf(z1, p1.x, fmaf(z2, p1.w, p2.z)));
    float y2 = fmaf(z0, p0.z, fmaf(z1, p1.y, fmaf(z2, p2.x, p2.w)));

    float e0 = __expf(-(sr0 + 2.0f));
    float e1 = __expf(-(sr1 + 2.0f));
    float e2 = __expf(-(sr2 + 2.0f));
    float d0 = 1.0f + e0, d1 = 1.0f + e1, d2 = 1.0f + e2;
    float rr = frcp(d0 * (d1 * d2));
    float s0 = fmaf(d1 * d2, rr, AFFINE_EPS);
    float s1 = fmaf(d0 * d2, rr, AFFINE_EPS);
    float s2 = fmaf(d0 * d1, rr, AFFINE_EPS);
    prod *= (s0 * s1) * s2;
    z0 = fmaf(y0, s0, sh0);
    z1 = fmaf(y1, s1, sh1);
    z2 = fmaf(y2, s2, sh2);
}

__device__ __forceinline__ void last_linear(
    const float* __restrict__ sWB,
    float& z0, float& z1, float& z2)
{
    const float4* L = (const float4*)(sWB + 12 * NL);
    float4 p0 = L[0], p1 = L[1], p2 = L[2];
    float y0 = fmaf(z0, p0.x, fmaf(z1, p0.w, fmaf(z2, p1.z, p2.y)));
    float y1 = fmaf(z0, p0.y, fmaf(z1, p1.x, fmaf(z2, p1.w, p2.z)));
    float y2 = fmaf(z0, p0.z, fmaf(z1, p1.y, fmaf(z2, p2.x, p2.w)));
    z0 = y0; z1 = y1; z2 = y2;
}

__global__ __launch_bounds__(ROWS, 7) void flow_kernel(
    const float* __restrict__ x,
    const float* __restrict__ aff,
    const float* __restrict__ Ws,
    const float* __restrict__ bs,
    const float* __restrict__ lW,
    const float* __restrict__ lb,
    float* __restrict__ z_out,
    float* __restrict__ ld_out,
    int n)
{
    // Single-shot staging tile for affine_info: 128 rows x 60 floats = 30720 B
    __shared__ __align__(16) float sA[ROWS * 60];
    // x-in / z-out bounce buffer: 128 rows x 3 floats = 1536 B
    __shared__ __align__(16) float sX[ROWS * 3];
    // 11 layers x 12 floats: [W0..W8, b0..b2]
    __shared__ __align__(16) float sWB[(NL + 1) * 12];
    __shared__ float sDet[NL + 1];

    int tid = threadIdx.x;
    size_t rowbase = (size_t)blockIdx.x * ROWS;
    int r = (int)rowbase + tid;
    bool full = (rowbase + ROWS <= (size_t)n);

    // --- Issue all async copies FIRST (one commit group, one wait) ---
    if (full) {
        unsigned sAb = (unsigned)__cvta_generic_to_shared(sA);
        unsigned sXb = (unsigned)__cvta_generic_to_shared(sX);
        const char* g = (const char*)(aff + rowbase * 60);
        // x stage: 1536 B = 96 coalesced float4 copies (L1 bypass)
        if (tid < 96) {
            const char* src = (const char*)(x + rowbase * 3) + (size_t)tid * 16;
            asm volatile("cp.async.cg.shared.global [%0], [%1], 16;\n"
                         :: "r"(sXb + (unsigned)tid * 16u), "l"(src));
        }
        // aff stage: 15 x 16B per thread, fully coalesced, linear layout
        #pragma unroll
        for (int m = 0; m < 15; m++) {
            unsigned l = (unsigned)(tid + ROWS * m);
            asm volatile("cp.async.cg.shared.global [%0], [%1], 16;\n"
                         :: "r"(sAb + l * 16u), "l"(g + (size_t)l * 16u));
        }
        asm volatile("cp.async.commit_group;\n");
    } else if (r < n) {
        // tail block: per-thread copy of own row
        const float4* A = (const float4*)(aff + (size_t)r * 60);
        float4* S = (float4*)(sA + tid * 60);
        #pragma unroll
        for (int m = 0; m < 15; m++) S[m] = A[m];
        sX[3 * tid + 0] = x[3 * r + 0];
        sX[3 * tid + 1] = x[3 * r + 1];
        sX[3 * tid + 2] = x[3 * r + 2];
    }

    // --- Stage weights (overlaps with cp.async flight time) ---
    for (int i = tid; i < (NL + 1) * 12; i += ROWS) {
        int layer = i / 12, j = i % 12;
        float val;
        if (layer < NL) val = (j < 9) ? Ws[layer * 9 + j] : bs[layer * 3 + (j - 9)];
        else            val = (j < 9) ? lW[j]             : lb[j - 9];
        sWB[i] = val;
    }
    // Parallel slogdet: one det-log per thread
    if (tid <= NL) {
        const float* W = (tid < NL) ? (Ws + 9 * tid) : lW;
        float det = W[0] * (W[4] * W[8] - W[5] * W[7])
                  - W[1] * (W[3] * W[8] - W[5] * W[6])
                  + W[2] * (W[3] * W[7] - W[4] * W[6]);
        sDet[tid] = __logf(fabsf(det));
    }

    if (full) asm volatile("cp.async.wait_group 0;\n");
    __syncthreads();

    if (r >= n) return;

    // Every thread sums the 11 det-logs (broadcast LDS, cheap)
    float sConst = 0.0f;
    #pragma unroll
    for (int i = 0; i <= NL; i++) sConst += sDet[i];

    // Read own row from smem: 15 x LDS.128, conflict-free per 8-lane phase
    float v[60];
    const float4* S = (const float4*)(sA + tid * 60);
    #pragma unroll
    for (int m = 0; m < 15; m++) {
        float4 t = S[m];
        v[4 * m + 0] = t.x; v[4 * m + 1] = t.y;
        v[4 * m + 2] = t.z; v[4 * m + 3] = t.w;
    }

    float z0 = sX[3 * tid + 0];
    float z1 = sX[3 * tid + 1];
    float z2 = sX[3 * tid + 2];

    float prod = 1.0f;   // running product of all 30 scales -> single log

    #pragma unroll
    for (int i = 0; i < NL; i++) {
        layer_step(sWB, i,
                   v[6 * i + 0], v[6 * i + 1], v[6 * i + 2],
                   v[6 * i + 3], v[6 * i + 4], v[6 * i + 5],
                   z0, z1, z2, prod);
    }
    last_linear(sWB, z0, z1, z2);

    float logdet = sConst + __logf(prod)
                 - 0.5f * fmaf(z0, z0, fmaf(z1, z1, z2 * z2))
                 - 1.5f * LOG2PI;

    if (full) {
        // Coalesced z store via bounce buffer (own-slot write, no race)
        sX[3 * tid + 0] = z0;
        sX[3 * tid + 1] = z1;
        sX[3 * tid + 2] = z2;
        __syncthreads();
        if (tid < 96) {
            float4* dst = (float4*)(z_out + rowbase * 3);
            const float4* src = (const float4*)sX;
            dst[tid] = src[tid];
        }
        ld_out[rowbase + tid] = logdet;
    } else {
        z_out[3 * r + 0] = z0;
        z_out[3 * r + 1] = z1;
        z_out[3 * r + 2] = z2;
        ld_out[r] = logdet;
    }
}

extern "C" void kernel_launch(void* const* d_in, const int* in_sizes, int n_in,
                              void* d_out, int out_size) {
    const float* x   = (const float*)d_in[0];
    const float* aff = (const float*)d_in[1];
    const float* Ws  = (const float*)d_in[2];
    const float* bs  = (const float*)d_in[3];
    const float* lW  = (const float*)d_in[4];
    const float* lb  = (const float*)d_in[5];

    int n = in_sizes[0] / 3;                 // N rows
    float* z_out  = (float*)d_out;           // [N, 3]
    float* ld_out = (float*)d_out + (size_t)3 * n;  // [N]

    int grid = (n + ROWS - 1) / ROWS;
    flow_kernel<<<grid, ROWS>>>(x, aff, Ws, bs, lW, lb, z_out, ld_out, n);
}

// round 16
// speedup vs baseline: 1.0004x; 1.0004x over previous
#include <cuda_runtime.h>
#include <cstdint>

#define NL 10
#define ROWS 128
#define AFFINE_EPS 1e-4f
#define LOG2PI 1.8378770664093453f

__device__ __forceinline__ float frcp(float x) {
    float r;
    asm("rcp.approx.f32 %0, %1;" : "=f"(r) : "f"(x));
    return r;
}

// One coupling layer: z = (z @ W + b) * scale + shift, prod *= s0*s1*s2
__device__ __forceinline__ void layer_step(
    const float* __restrict__ sWB, int i,
    float sr0, float sr1, float sr2,
    float sh0, float sh1, float sh2,
    float& z0, float& z1, float& z2, float& prod)
{
    const float4* L = (const float4*)(sWB + 12 * i);
    float4 p0 = L[0], p1 = L[1], p2 = L[2];
    // W row-major: p0 = W[0..3], p1 = W[4..7], p2.x = W[8], p2.yzw = b
    float y0 = fmaf(z0, p0.x, fmaf(z1, p0.w, fmaf(z2, p1.z, p2.y)));
    float y1 = fmaf(z0, p0.y, fmaf(z1, p1.x, fmaf(z2, p1.w, p2.z)));
    float y2 = fmaf(z0, p0.z, fmaf(z1, p1.y, fmaf(z2, p2.x, p2.w)));

    float e0 = __expf(-(sr0 + 2.0f));
    float e1 = __expf(-(sr1 + 2.0f));
    float e2 = __expf(-(sr2 + 2.0f));
    float d0 = 1.0f + e0, d1 = 1.0f + e1, d2 = 1.0f + e2;
    float rr = frcp(d0 * (d1 * d2));
    float s0 = fmaf(d1 * d2, rr, AFFINE_EPS);
    float s1 = fmaf(d0 * d2, rr, AFFINE_EPS);
    float s2 = fmaf(d0 * d1, rr, AFFINE_EPS);
    prod *= (s0 * s1) * s2;
    z0 = fmaf(y0, s0, sh0);
    z1 = fmaf(y1, s1, sh1);
    z2 = fmaf(y2, s2, sh2);
}

__device__ __forceinline__ void last_linear(
    const float* __restrict__ sWB,
    float& z0, float& z1, float& z2)
{
    const float4* L = (const float4*)(sWB + 12 * NL);
    float4 p0 = L[0], p1 = L[1], p2 = L[2];
    float y0 = fmaf(z0, p0.x, fmaf(z1, p0.w, fmaf(z2, p1.z, p2.y)));
    float y1 = fmaf(z0, p0.y, fmaf(z1, p1.x, fmaf(z2, p1.w, p2.z)));
    float y2 = fmaf(z0, p0.z, fmaf(z1, p1.y, fmaf(z2, p2.x, p2.w)));
    z0 = y0; z1 = y1; z2 = y2;
}

__global__ __launch_bounds__(ROWS, 7) void flow_kernel(
    const float* __restrict__ x,
    const float* __restrict__ aff,
    const float* __restrict__ Ws,
    const float* __restrict__ bs,
    const float* __restrict__ lW,
    const float* __restrict__ lb,
    float* __restrict__ z_out,
    float* __restrict__ ld_out,
    int n)
{
    // Single-shot staging tile for affine_info: 128 rows x 60 floats = 30720 B
    __shared__ __align__(16) float sA[ROWS * 60];
    // x-in / z-out bounce buffer: 128 rows x 3 floats = 1536 B
    __shared__ __align__(16) float sX[ROWS * 3];
    // 11 layers x 12 floats: [W0..W8, b0..b2]
    __shared__ __align__(16) float sWB[(NL + 1) * 12];
    __shared__ float sDet[NL + 1];

    int tid = threadIdx.x;
    size_t rowbase = (size_t)blockIdx.x * ROWS;
    int r = (int)rowbase + tid;
    bool full = (rowbase + ROWS <= (size_t)n);

    // --- Issue all async copies FIRST (one commit group, one wait) ---
    if (full) {
        unsigned sAb = (unsigned)__cvta_generic_to_shared(sA);
        unsigned sXb = (unsigned)__cvta_generic_to_shared(sX);
        const char* g = (const char*)(aff + rowbase * 60);
        // x stage: 1536 B = 96 coalesced float4 copies (L1 bypass)
        if (tid < 96) {
            const char* src = (const char*)(x + rowbase * 3) + (size_t)tid * 16;
            asm volatile("cp.async.cg.shared.global [%0], [%1], 16;\n"
                         :: "r"(sXb + (unsigned)tid * 16u), "l"(src));
        }
        // aff stage: 15 x 16B per thread, fully coalesced, linear layout
        #pragma unroll
        for (int m = 0; m < 15; m++) {
            unsigned l = (unsigned)(tid + ROWS * m);
            asm volatile("cp.async.cg.shared.global [%0], [%1], 16;\n"
                         :: "r"(sAb + l * 16u), "l"(g + (size_t)l * 16u));
        }
        asm volatile("cp.async.commit_group;\n");
    } else if (r < n) {
        // tail block: per-thread copy of own row
        const float4* A = (const float4*)(aff + (size_t)r * 60);
        float4* S = (float4*)(sA + tid * 60);
        #pragma unroll
        for (int m = 0; m < 15; m++) S[m] = A[m];
        sX[3 * tid + 0] = x[3 * r + 0];
        sX[3 * tid + 1] = x[3 * r + 1];
        sX[3 * tid + 2] = x[3 * r + 2];
    }

    // --- Stage weights (overlaps with cp.async flight time) ---
    for (int i = tid; i < (NL + 1) * 12; i += ROWS) {
        int layer = i / 12, j = i % 12;
        float val;
        if (layer < NL) val = (j < 9) ? Ws[layer * 9 + j] : bs[layer * 3 + (j - 9)];
        else            val = (j < 9) ? lW[j]             : lb[j - 9];
        sWB[i] = val;
    }
    // Parallel slogdet: one det-log per thread
    if (tid <= NL) {
        const float* W = (tid < NL) ? (Ws + 9 * tid) : lW;
        float det = W[0] * (W[4] * W[8] - W[5] * W[7])
                  - W[1] * (W[3] * W[8] - W[5] * W[6])
                  + W[2] * (W[3] * W[7] - W[4] * W[6]);
        sDet[tid] = __logf(fabsf(det));
    }

    if (full) asm volatile("cp.async.wait_group 0;\n");
    __syncthreads();

    if (r >= n) return;

    // Every thread sums the 11 det-logs (broadcast LDS, cheap)
    float sConst = 0.0f;
    #pragma unroll
    for (int i = 0; i <= NL; i++) sConst += sDet[i];

    // Read own row from smem: 15 x LDS.128, conflict-free per 8-lane phase
    float v[60];
    const float4* S = (const float4*)(sA + tid * 60);
    #pragma unroll
    for (int m = 0; m < 15; m++) {
        float4 t = S[m];
        v[4 * m + 0] = t.x; v[4 * m + 1] = t.y;
        v[4 * m + 2] = t.z; v[4 * m + 3] = t.w;
    }

    float z0 = sX[3 * tid + 0];
    float z1 = sX[3 * tid + 1];
    float z2 = sX[3 * tid + 2];

    float prod = 1.0f;   // running product of all 30 scales -> single log

    #pragma unroll
    for (int i = 0; i < NL; i++) {
        layer_step(sWB, i,
                   v[6 * i + 0], v[6 * i + 1], v[6 * i + 2],
                   v[6 * i + 3], v[6 * i + 4], v[6 * i + 5],
                   z0, z1, z2, prod);
    }
    last_linear(sWB, z0, z1, z2);

    float logdet = sConst + __logf(prod)
                 - 0.5f * fmaf(z0, z0, fmaf(z1, z1, z2 * z2))
                 - 1.5f * LOG2PI;

    if (full) {
        // Coalesced z store via bounce buffer (own-slot write, no race)
        sX[3 * tid + 0] = z0;
        sX[3 * tid + 1] = z1;
        sX[3 * tid + 2] = z2;
        __syncthreads();
        if (tid < 96) {
            float4* dst = (float4*)(z_out + rowbase * 3);
            const float4* src = (const float4*)sX;
            dst[tid] = src[tid];
        }
        ld_out[rowbase + tid] = logdet;
    } else {
        z_out[3 * r + 0] = z0;
        z_out[3 * r + 1] = z1;
        z_out[3 * r + 2] = z2;
        ld_out[r] = logdet;
    }
}

extern "C" void kernel_launch(void* const* d_in, const int* in_sizes, int n_in,
                              void* d_out, int out_size) {
    const float* x   = (const float*)d_in[0];
    const float* aff = (const float*)d_in[1];
    const float* Ws  = (const float*)d_in[2];
    const float* bs  = (const float*)d_in[3];
    const float* lW  = (const float*)d_in[4];
    const float* lb  = (const float*)d_in[5];

    int n = in_sizes[0] / 3;                 // N rows
    float* z_out  = (float*)d_out;           // [N, 3]
    float* ld_out = (float*)d_out + (size_t)3 * n;  // [N]

    int grid = (n + ROWS - 1) / ROWS;
    flow_kernel<<<grid, ROWS>>>(x, aff, Ws, bs, lW, lb, z_out, ld_out, n);
}

// round 17
// speedup vs baseline: 1.0042x; 1.0038x over previous
#include <cuda_runtime.h>
#include <cstdint>

#define NL 10
#define ROWS 256
#define AFFINE_EPS 1e-4f
#define LOG2PI 1.8378770664093453f

// dynamic smem layout (bytes)
#define OFF_SA   0                       // 256 x 60 floats = 61440
#define OFF_SX   61440                   // 256 x 3 floats  = 3072
#define OFF_SWB  64512                   // 132 floats = 528
#define OFF_SDET 65040                   // 11 floats = 44
#define SMEM_TOTAL 65088

__device__ __forceinline__ float frcp(float x) {
    float r;
    asm("rcp.approx.f32 %0, %1;" : "=f"(r) : "f"(x));
    return r;
}

// One coupling layer: z = (z @ W + b) * scale + shift, prod *= s0*s1*s2
__device__ __forceinline__ void layer_step(
    const float* __restrict__ sWB, int i,
    float sr0, float sr1, float sr2,
    float sh0, float sh1, float sh2,
    float& z0, float& z1, float& z2, float& prod)
{
    const float4* L = (const float4*)(sWB + 12 * i);
    float4 p0 = L[0], p1 = L[1], p2 = L[2];
    // W row-major: p0 = W[0..3], p1 = W[4..7], p2.x = W[8], p2.yzw = b
    float y0 = fmaf(z0, p0.x, fmaf(z1, p0.w, fmaf(z2, p1.z, p2.y)));
    float y1 = fmaf(z0, p0.y, fmaf(z1, p1.x, fmaf(z2, p1.w, p2.z)));
    float y2 = fmaf(z0, p0.z, fmaf(z1, p1.y, fmaf(z2, p2.x, p2.w)));

    float e0 = __expf(-(sr0 + 2.0f));
    float e1 = __expf(-(sr1 + 2.0f));
    float e2 = __expf(-(sr2 + 2.0f));
    float d0 = 1.0f + e0, d1 = 1.0f + e1, d2 = 1.0f + e2;
    float rr = frcp(d0 * (d1 * d2));
    float s0 = fmaf(d1 * d2, rr, AFFINE_EPS);
    float s1 = fmaf(d0 * d2, rr, AFFINE_EPS);
    float s2 = fmaf(d0 * d1, rr, AFFINE_EPS);
    prod *= (s0 * s1) * s2;
    z0 = fmaf(y0, s0, sh0);
    z1 = fmaf(y1, s1, sh1);
    z2 = fmaf(y2, s2, sh2);
}

__device__ __forceinline__ void last_linear(
    const float* __restrict__ sWB,
    float& z0, float& z1, float& z2)
{
    const float4* L = (const float4*)(sWB + 12 * NL);
    float4 p0 = L[0], p1 = L[1], p2 = L[2];
    float y0 = fmaf(z0, p0.x, fmaf(z1, p0.w, fmaf(z2, p1.z, p2.y)));
    float y1 = fmaf(z0, p0.y, fmaf(z1, p1.x, fmaf(z2, p1.w, p2.z)));
    float y2 = fmaf(z0, p0.z, fmaf(z1, p1.y, fmaf(z2, p2.x, p2.w)));
    z0 = y0; z1 = y1; z2 = y2;
}

__global__ __launch_bounds__(ROWS, 3) void flow_kernel(
    const float* __restrict__ x,
    const float* __restrict__ aff,
    const float* __restrict__ Ws,
    const float* __restrict__ bs,
    const float* __restrict__ lW,
    const float* __restrict__ lb,
    float* __restrict__ z_out,
    float* __restrict__ ld_out,
    int n)
{
    extern __shared__ __align__(16) char smem[];
    float* sA   = (float*)(smem + OFF_SA);    // [256*60]
    float* sX   = (float*)(smem + OFF_SX);    // [256*3]
    float* sWB  = (float*)(smem + OFF_SWB);   // [(NL+1)*12]
    float* sDet = (float*)(smem + OFF_SDET);  // [NL+1]

    int tid = threadIdx.x;
    size_t rowbase = (size_t)blockIdx.x * ROWS;
    int r = (int)rowbase + tid;
    bool full = (rowbase + ROWS <= (size_t)n);

    // --- Issue all async copies FIRST (one commit group, one wait) ---
    if (full) {
        unsigned sAb = (unsigned)__cvta_generic_to_shared(sA);
        unsigned sXb = (unsigned)__cvta_generic_to_shared(sX);
        const char* g = (const char*)(aff + rowbase * 60);
        // x stage: 3072 B = 192 coalesced float4 copies (L1 bypass)
        if (tid < 192) {
            const char* src = (const char*)(x + rowbase * 3) + (size_t)tid * 16;
            asm volatile("cp.async.cg.shared.global [%0], [%1], 16;\n"
                         :: "r"(sXb + (unsigned)tid * 16u), "l"(src));
        }
        // aff stage: 15 x 16B per thread, fully coalesced, linear layout
        #pragma unroll
        for (int m = 0; m < 15; m++) {
            unsigned l = (unsigned)(tid + ROWS * m);
            asm volatile("cp.async.cg.shared.global [%0], [%1], 16;\n"
                         :: "r"(sAb + l * 16u), "l"(g + (size_t)l * 16u));
        }
        asm volatile("cp.async.commit_group;\n");
    } else if (r < n) {
        // tail block: per-thread copy of own row
        const float4* A = (const float4*)(aff + (size_t)r * 60);
        float4* S = (float4*)(sA + tid * 60);
        #pragma unroll
        for (int m = 0; m < 15; m++) S[m] = A[m];
        sX[3 * tid + 0] = x[3 * r + 0];
        sX[3 * tid + 1] = x[3 * r + 1];
        sX[3 * tid + 2] = x[3 * r + 2];
    }

    // --- Stage weights (overlaps with cp.async flight time) ---
    if (tid < (NL + 1) * 12) {
        int layer = tid / 12, j = tid % 12;
        float val;
        if (layer < NL) val = (j < 9) ? Ws[layer * 9 + j] : bs[layer * 3 + (j - 9)];
        else            val = (j < 9) ? lW[j]             : lb[j - 9];
        sWB[tid] = val;
    }
    // Parallel slogdet: one det-log per thread (use high lanes, different warp)
    if (tid >= 224 && tid <= 224 + NL) {
        int i = tid - 224;
        const float* W = (i < NL) ? (Ws + 9 * i) : lW;
        float det = W[0] * (W[4] * W[8] - W[5] * W[7])
                  - W[1] * (W[3] * W[8] - W[5] * W[6])
                  + W[2] * (W[3] * W[7] - W[4] * W[6]);
        sDet[i] = __logf(fabsf(det));
    }

    if (full) asm volatile("cp.async.wait_group 0;\n");
    __syncthreads();

    if (r >= n) return;

    // Every thread sums the 11 det-logs (broadcast LDS, cheap)
    float sConst = 0.0f;
    #pragma unroll
    for (int i = 0; i <= NL; i++) sConst += sDet[i];

    // Read own row from smem: 15 x LDS.128, conflict-free per 8-lane phase
    float v[60];
    const float4* S = (const float4*)(sA + tid * 60);
    #pragma unroll
    for (int m = 0; m < 15; m++) {
        float4 t = S[m];
        v[4 * m + 0] = t.x; v[4 * m + 1] = t.y;
        v[4 * m + 2] = t.z; v[4 * m + 3] = t.w;
    }

    float z0 = sX[3 * tid + 0];
    float z1 = sX[3 * tid + 1];
    float z2 = sX[3 * tid + 2];

    float prod = 1.0f;   // running product of all 30 scales -> single log

    #pragma unroll
    for (int i = 0; i < NL; i++) {
        layer_step(sWB, i,
                   v[6 * i + 0], v[6 * i + 1], v[6 * i + 2],
                   v[6 * i + 3], v[6 * i + 4], v[6 * i + 5],
                   z0, z1, z2, prod);
    }
    last_linear(sWB, z0, z1, z2);

    float logdet = sConst + __logf(prod)
                 - 0.5f * fmaf(z0, z0, fmaf(z1, z1, z2 * z2))
                 - 1.5f * LOG2PI;

    if (full) {
        // Coalesced z store via bounce buffer (own-slot write, no race)
        sX[3 * tid + 0] = z0;
        sX[3 * tid + 1] = z1;
        sX[3 * tid + 2] = z2;
        __syncthreads();
        if (tid < 192) {
            float4* dst = (float4*)(z_out + rowbase * 3);
            const float4* src = (const float4*)sX;
            dst[tid] = src[tid];
        }
        ld_out[rowbase + tid] = logdet;
    } else {
        z_out[3 * r + 0] = z0;
        z_out[3 * r + 1] = z1;
        z_out[3 * r + 2] = z2;
        ld_out[r] = logdet;
    }
}

extern "C" void kernel_launch(void* const* d_in, const int* in_sizes, int n_in,
                              void* d_out, int out_size) {
    const float* x   = (const float*)d_in[0];
    const float* aff = (const float*)d_in[1];
    const float* Ws  = (const float*)d_in[2];
    const float* bs  = (const float*)d_in[3];
    const float* lW  = (const float*)d_in[4];
    const float* lb  = (const float*)d_in[5];

    int n = in_sizes[0] / 3;                 // N rows
    float* z_out  = (float*)d_out;           // [N, 3]
    float* ld_out = (float*)d_out + (size_t)3 * n;  // [N]

    cudaFuncSetAttribute(flow_kernel,
                         cudaFuncAttributeMaxDynamicSharedMemorySize, SMEM_TOTAL);

    int grid = (n + ROWS - 1) / ROWS;
    flow_kernel<<<grid, ROWS, SMEM_TOTAL>>>(x, aff, Ws, bs, lW, lb,
                                            z_out, ld_out, n);
}